// round 12
// baseline (speedup 1.0000x reference)
#include <cuda_runtime.h>
#include <cuda_fp16.h>
#include <stdint.h>

// Problem constants (B, D, F, target_l0) — fixed by the dataset.
#define NB 1024
#define ND 1024
#define NF 32768
#define L0 32
#define EPSF 1e-3f
#define NTILE (NF / 128)        // 256 column tiles

// ---------------- device state (no allocations allowed) ----------------
__device__ float              g_res[NB * ND];            // residual [B,D] fp32
__device__ float              g_rnorm[NB];               // ||r|| per row
__device__ __half             g_rhi[NB * ND];            // residual fp16
__device__ __half             g_xhi[(size_t)NF * ND];    // xs fp16
__device__ unsigned long long g_t2[(size_t)NB * NTILE * 2];  // per (row,tile) top-2 keys
__device__ float              g_w[NB * L0];
__device__ int                g_idx[NB * L0];
__device__ int                g_cnt[NB];

// ---------------- helpers ----------------
__device__ __forceinline__ uint32_t smem_to_u32(const void* p) {
    uint32_t a;
    asm("{ .reg .u64 t; cvta.to.shared.u64 t, %1; cvt.u32.u64 %0, t; }" : "=r"(a) : "l"(p));
    return a;
}

// pack (value, index): larger key == (larger value, then smaller index)
__device__ __forceinline__ unsigned long long pack_key(float v, int idx) {
    unsigned u = __float_as_uint(v);
    u = (u & 0x80000000u) ? ~u : (u | 0x80000000u);
    return ((unsigned long long)u << 32) | (unsigned)(0xFFFFFFFFu - (unsigned)idx);
}
__device__ __forceinline__ float unpack_val(unsigned long long k) {
    unsigned u = (unsigned)(k >> 32);
    u = (u & 0x80000000u) ? (u ^ 0x80000000u) : ~u;
    return __uint_as_float(u);
}
__device__ __forceinline__ int unpack_idx(unsigned long long k) {
    return (int)(0xFFFFFFFFu - (unsigned)(k & 0xFFFFFFFFull));
}

#define LDSM4(f, addr)                                                                 \
    asm volatile("ldmatrix.sync.aligned.m8n8.x4.shared.b16 {%0,%1,%2,%3}, [%4];"       \
                 : "=r"((f)[0]), "=r"((f)[1]), "=r"((f)[2]), "=r"((f)[3]) : "r"(addr))

#define MMA16816(d, a, b0, b1)                                                         \
    asm volatile("mma.sync.aligned.m16n8k16.row.col.f32.f16.f16.f32 "                  \
                 "{%0,%1,%2,%3},{%4,%5,%6,%7},{%8,%9},{%0,%1,%2,%3};"                  \
                 : "+f"((d)[0]), "+f"((d)[1]), "+f"((d)[2]), "+f"((d)[3])              \
                 : "r"((a)[0]), "r"((a)[1]), "r"((a)[2]), "r"((a)[3]),                 \
                   "r"(b0), "r"(b1))

#define CP_ASYNC16(sa, gp) \
    asm volatile("cp.async.cg.shared.global [%0], [%1], 16;" :: "r"(sa), "l"(gp))
#define CP_COMMIT()  asm volatile("cp.async.commit_group;")
#define CP_WAIT(n)   asm volatile("cp.async.wait_group %0;" :: "n"(n))

// ---------------- K-1: one-time fp16 cast of xs ----------------
__global__ void k_split_xs(const float* __restrict__ xs) {
    size_t i = (size_t)blockIdx.x * blockDim.x + threadIdx.x;
    size_t n4 = (size_t)NF * ND / 4;
    if (i >= n4) return;
    float4 v = ((const float4*)xs)[i];
    __half2* ph = (__half2*)g_xhi;
    ph[i * 2 + 0] = __half2(__float2half_rn(v.x), __float2half_rn(v.y));
    ph[i * 2 + 1] = __half2(__float2half_rn(v.z), __float2half_rn(v.w));
}

// ---------------- K0: init ----------------
__global__ void k_init(const float* __restrict__ x) {
    int i = blockIdx.x * blockDim.x + threadIdx.x;
    if (i < NB * ND) {
        float v = x[i];
        g_res[i] = v;
        g_rhi[i] = __float2half_rn(v);
    }
    if (i < NB) g_cnt[i] = 0;
}

// initial residual norms
__global__ __launch_bounds__(256) void k_norm0() {
    const int b = blockIdx.x;
    const int tid = threadIdx.x;
    __shared__ float wr[8];
    float nn = 0.f;
    for (int d = tid; d < ND; d += 256) {
        float v = g_res[(size_t)b * ND + d];
        nn = fmaf(v, v, nn);
    }
#pragma unroll
    for (int o = 16; o; o >>= 1) nn += __shfl_xor_sync(0xffffffffu, nn, o);
    if ((tid & 31) == 0) wr[tid >> 5] = nn;
    __syncthreads();
    if (tid == 0) {
        float t = 0.f;
        for (int i = 0; i < 8; i++) t += wr[i];
        g_rnorm[b] = sqrtf(t);
    }
}

// ---------------- K2: fp16 hi*hi GEMM (mma.sync) -> per-(row,tile) top-2 keys ----------------
// CTA tile 128(M) x 128(N), BK=64 (128B fp16 rows, XOR swizzle), 2-stage cp.async (R6 config).
#define MAT_BYTES 16384                 // 128 rows * 128B
#define STAGE_BYTES (2 * MAT_BYTES)     // aH, bH
#define GSMEM (2 * STAGE_BYTES)         // 65536

__device__ __forceinline__ void fill_stage(uint32_t st, int k0, int tid,
                                           const __half* aH, const __half* bH) {
#pragma unroll
    for (int it = 0; it < 8; it++) {
        const int mat = it >> 2;                 // 0 = A, 1 = B
        const int w = (it & 3) * 256 + tid;      // 0..1023 within matrix
        const int row = w >> 3;
        const int c = w & 7;
        const __half* base = mat ? bH : aH;
        const __half* gp = base + (size_t)row * ND + k0 + c * 8;
        uint32_t off = (uint32_t)(row * 128 + ((c ^ (row & 7)) * 16));
        CP_ASYNC16(st + mat * MAT_BYTES + off, gp);
    }
    CP_COMMIT();
}

__global__ __launch_bounds__(256, 2) void k_gemm_mma() {
    extern __shared__ char smem[];
    const uint32_t sb = smem_to_u32(smem);

    const int tid = threadIdx.x;
    const int lane = tid & 31;
    const int wid = tid >> 5;
    const int wm = wid >> 1;      // 0..3 (M)
    const int wn = wid & 1;       // 0..1 (N)
    const int mi = lane >> 3;
    const int r8 = lane & 7;

    const int id = blockIdx.x;
    const int by = id & 7;        // M tiles vary fastest -> CTAs share B tile in L2
    const int bx = id >> 3;
    const int row0 = by * 128;
    const int col0 = bx * 128;

    const __half* aH = g_rhi + (size_t)row0 * ND;
    const __half* bH = g_xhi + (size_t)col0 * ND;

    float acc[2][8][4];
#pragma unroll
    for (int i = 0; i < 2; i++)
#pragma unroll
        for (int j = 0; j < 8; j++)
#pragma unroll
            for (int q = 0; q < 4; q++) acc[i][j][q] = 0.f;

    fill_stage(sb, 0, tid, aH, bH);
    fill_stage(sb + STAGE_BYTES, 64, tid, aH, bH);
    CP_WAIT(1);
    __syncthreads();

    int buf = 0;
    for (int cch = 0; cch < 16; cch++) {
        const uint32_t st = sb + buf * STAGE_BYTES;

#pragma unroll
        for (int k16 = 0; k16 < 4; k16++) {
            uint32_t afr[2][4];
#pragma unroll
            for (int mt = 0; mt < 2; mt++) {
                const int row = wm * 32 + mt * 16 + (mi & 1) * 8 + r8;
                const int kc = k16 * 2 + (mi >> 1);
                const uint32_t off = (uint32_t)(row * 128 + ((kc ^ (row & 7)) * 16));
                LDSM4(afr[mt], st + off);
            }
            uint32_t bfr[4][4];
#pragma unroll
            for (int nt = 0; nt < 4; nt++) {
                const int row = wn * 64 + nt * 16 + (mi >> 1) * 8 + r8;
                const int kc = k16 * 2 + (mi & 1);
                const uint32_t off = (uint32_t)(row * 128 + ((kc ^ (row & 7)) * 16));
                LDSM4(bfr[nt], st + MAT_BYTES + off);
            }
#pragma unroll
            for (int mt = 0; mt < 2; mt++)
#pragma unroll
                for (int nt = 0; nt < 4; nt++)
#pragma unroll
                    for (int s = 0; s < 2; s++)
                        MMA16816(acc[mt][nt * 2 + s], afr[mt],
                                 bfr[nt][s * 2], bfr[nt][s * 2 + 1]);
        }

        __syncthreads();
        if (cch + 2 < 16) {
            fill_stage(sb + buf * STAGE_BYTES, (cch + 2) * 64, tid, aH, bH);
            CP_WAIT(1);
        } else {
            CP_WAIT(0);
        }
        __syncthreads();
        buf ^= 1;
    }

    // ---- epilogue: per-(row, 128-col tile) top-2 packed keys from fp32 acc ----
    unsigned long long (*s_t2)[2][2] = (unsigned long long (*)[2][2])smem;  // [128][wn][2]
#pragma unroll
    for (int mt = 0; mt < 2; mt++) {
#pragma unroll
        for (int goff = 0; goff < 2; goff++) {
            unsigned long long k1 = 0ull, k2 = 0ull;
            const int colbase = col0 + wn * 64 + (lane & 3) * 2;
#pragma unroll
            for (int j = 0; j < 8; j++) {
                unsigned long long ka = pack_key(acc[mt][j][goff * 2 + 0], colbase + j * 8);
                unsigned long long kb = pack_key(acc[mt][j][goff * 2 + 1], colbase + j * 8 + 1);
                if (ka > k1) { k2 = k1; k1 = ka; } else if (ka > k2) k2 = ka;
                if (kb > k1) { k2 = k1; k1 = kb; } else if (kb > k2) k2 = kb;
            }
#pragma unroll
            for (int o = 1; o < 4; o <<= 1) {
                unsigned long long ok1 = __shfl_xor_sync(0xffffffffu, k1, o);
                unsigned long long ok2 = __shfl_xor_sync(0xffffffffu, k2, o);
                unsigned long long lo = (k1 > ok1) ? k2 : ok2;
                unsigned long long mn = (k1 > ok1) ? ok1 : k1;
                k1 = (k1 > ok1) ? k1 : ok1;
                k2 = (mn > lo) ? mn : lo;
            }
            if ((lane & 3) == 0) {
                const int rl = wm * 32 + mt * 16 + goff * 8 + (lane >> 2);
                s_t2[rl][wn][0] = k1;
                s_t2[rl][wn][1] = k2;
            }
        }
    }
    __syncthreads();
    if (tid < 128) {
        unsigned long long a1 = s_t2[tid][0][0], a2 = s_t2[tid][0][1];
        unsigned long long b1 = s_t2[tid][1][0], b2 = s_t2[tid][1][1];
        unsigned long long k1 = (a1 > b1) ? a1 : b1;
        unsigned long long mn = (a1 > b1) ? b1 : a1;
        unsigned long long lo = (a1 > b1) ? a2 : b2;
        unsigned long long k2 = (mn > lo) ? mn : lo;
        const size_t base = ((size_t)(row0 + tid) * NTILE + bx) * 2;
        g_t2[base + 0] = k1;
        g_t2[base + 1] = k2;
    }
}

// ---------------- K3: fused rescue + update (one block of 256 per row) ----------------
// Candidates from top-2 keys; tiles whose top-2 clears thr get a full exact fp32 scan.
// Warp-parallel g-pass, smem c, algebraic rebuild.
#define MAXCAND 256
__global__ __launch_bounds__(256) void k_step(const float* __restrict__ x,
                                              const float* __restrict__ xs) {
    const int b = blockIdx.x;
    const int tid = threadIdx.x;
    const int warp = tid >> 5, lane = tid & 31;

    __shared__ unsigned long long s_kr[8];
    __shared__ float s_thr;
    __shared__ int   s_cand[MAXCAND];
    __shared__ int   s_nc;
    __shared__ int   s_ftiles[NTILE];
    __shared__ int   s_nft;
    __shared__ unsigned long long s_best;
    __shared__ int   s_idx[L0];
    __shared__ float s_w[L0];
    __shared__ float s_g[L0];
    __shared__ int   s_cnt;
    __shared__ float s_step;
    __shared__ int   s_dropidx[L0];
    __shared__ float s_dropw[L0];
    __shared__ int   s_ndrop;
    __shared__ float s_c[ND];
    __shared__ float w_cc[8], w_cr[8], w_nn[8];

    // ---- A1: load per-tile top-2 keys; block max over top-1 ----
    const size_t tbase = ((size_t)b * NTILE + tid) * 2;
    const unsigned long long t1k = g_t2[tbase + 0];
    const unsigned long long t2k = g_t2[tbase + 1];
    unsigned long long bk = t1k;
#pragma unroll
    for (int o = 16; o; o >>= 1) {
        unsigned long long ok = __shfl_xor_sync(0xffffffffu, bk, o);
        if (ok > bk) bk = ok;
    }
    if (lane == 0) s_kr[warp] = bk;
    if (tid == 0) { s_nc = 0; s_nft = 0; s_best = 0ull; s_ndrop = 0; }
    __syncthreads();
    if (tid == 0) {
        unsigned long long t = 0ull;
        for (int i = 0; i < 8; i++) if (s_kr[i] > t) t = s_kr[i];
        const float Bm = 2.0e-3f * g_rnorm[b] + 1e-7f;
        s_thr = unpack_val(t) - 2.f * Bm;
    }
    __syncthreads();
    const float thr = s_thr;

    // ---- A2: collect candidates + full-scan tiles ----
    if (unpack_val(t1k) >= thr) {
        int p = atomicAdd(&s_nc, 1);
        if (p < MAXCAND) s_cand[p] = unpack_idx(t1k);
    }
    if (unpack_val(t2k) >= thr) {
        int p = atomicAdd(&s_nc, 1);
        if (p < MAXCAND) s_cand[p] = unpack_idx(t2k);
        int q = atomicAdd(&s_nft, 1);
        s_ftiles[q] = tid;               // 3rd-best in this tile could clear thr too
    }
    __syncthreads();
    const int nc = (s_nc < MAXCAND) ? s_nc : MAXCAND;
    const int nft = s_nft;

    // ---- A3: exact fp32 rescore, one warp per candidate ----
    const float* r = g_res + (size_t)b * ND;
    for (int cdx = warp; cdx < nc; cdx += 8) {
        const int f = s_cand[cdx];
        const float* a = xs + (size_t)f * ND;
        float s = 0.f;
        for (int d = lane; d < ND; d += 32) s = fmaf(r[d], a[d], s);
#pragma unroll
        for (int o = 16; o; o >>= 1) s += __shfl_xor_sync(0xffffffffu, s, o);
        if (lane == 0) atomicMax(&s_best, pack_key(s, f));
    }
    // ---- A3b: full exact scan of flagged tiles (rare) ----
    for (int tt = 0; tt < nft; tt++) {
        const int tile = s_ftiles[tt];
        for (int j = warp; j < 128; j += 8) {
            const int f = tile * 128 + j;
            const float* a = xs + (size_t)f * ND;
            float s = 0.f;
            for (int d = lane; d < ND; d += 32) s = fmaf(r[d], a[d], s);
#pragma unroll
            for (int o = 16; o; o >>= 1) s += __shfl_xor_sync(0xffffffffu, s, o);
            if (lane == 0) atomicMax(&s_best, pack_key(s, f));
        }
    }
    __syncthreads();

    // ---- B: build active set ----
    if (tid == 0) {
        int cnt = g_cnt[b];
        for (int j = 0; j < cnt; j++) { s_idx[j] = g_idx[b * L0 + j]; s_w[j] = g_w[b * L0 + j]; }
        int f = unpack_idx(s_best);
        bool present = false;
        for (int j = 0; j < cnt; j++) if (s_idx[j] == f) { present = true; break; }
        if (!present) { s_idx[cnt] = f; s_w[cnt] = 0.f; cnt++; }
        s_cnt = cnt;
    }
    __syncthreads();
    const int m = s_cnt;

    // ---- g_j = <r, xs[f_j]>, warp-parallel (8 concurrent streams) ----
    for (int j = warp; j < m; j += 8) {
        const float* a = xs + (size_t)s_idx[j] * ND;
        float s = 0.f;
        for (int d = lane; d < ND; d += 32) s = fmaf(r[d], a[d], s);
#pragma unroll
        for (int o = 16; o; o >>= 1) s += __shfl_xor_sync(0xffffffffu, s, o);
        if (lane == 0) s_g[j] = s;
    }
    __syncthreads();

    // ---- c[d] = sum_j g_j xs_j[d] (kept in smem, xs rows L2-hot); cc, cr ----
    float cc = 0.f, cr = 0.f;
    for (int d = tid; d < ND; d += 256) {
        float c = 0.f;
        for (int j = 0; j < m; j++) c = fmaf(s_g[j], xs[(size_t)s_idx[j] * ND + d], c);
        s_c[d] = c;
        cc = fmaf(c, c, cc);
        cr = fmaf(c, r[d], cr);
    }
#pragma unroll
    for (int o = 16; o; o >>= 1) {
        cc += __shfl_xor_sync(0xffffffffu, cc, o);
        cr += __shfl_xor_sync(0xffffffffu, cr, o);
    }
    if (lane == 0) { w_cc[warp] = cc; w_cr[warp] = cr; }
    __syncthreads();
    if (tid == 0) {
        float tcc = 0.f, tcr = 0.f;
        for (int wv = 0; wv < 8; wv++) { tcc += w_cc[wv]; tcr += w_cr[wv]; }
        s_step = tcr / fmaxf(tcc, EPSF);
    }
    __syncthreads();
    const float step = s_step;

    // ---- relu update + compaction, recording dropped atoms ----
    if (tid == 0) {
        int ncn = 0, nd2 = 0;
        for (int j = 0; j < m; j++) {
            float wt = s_w[j] + step * s_g[j];
            if (wt > 0.f) { s_idx[ncn] = s_idx[j]; s_w[ncn] = wt; ncn++; }
            else          { s_dropidx[nd2] = s_idx[j]; s_dropw[nd2] = wt; nd2++; }
        }
        s_cnt = ncn;
        s_ndrop = nd2;
        g_cnt[b] = ncn;
        for (int j = 0; j < ncn; j++) { g_idx[b * L0 + j] = s_idx[j]; g_w[b * L0 + j] = s_w[j]; }
    }
    __syncthreads();
    const int nd = s_ndrop;

    // ---- algebraic rebuild: r_new = (r_old - step*c) + sum_dropped wtent*xs ----
    float nn = 0.f;
    for (int d = tid; d < ND; d += 256) {
        float v = fmaf(-step, s_c[d], g_res[(size_t)b * ND + d]);
        for (int dq = 0; dq < nd; dq++)
            v = fmaf(s_dropw[dq], xs[(size_t)s_dropidx[dq] * ND + d], v);
        g_res[(size_t)b * ND + d] = v;
        g_rhi[(size_t)b * ND + d] = __float2half_rn(v);
        nn = fmaf(v, v, nn);
    }
#pragma unroll
    for (int o = 16; o; o >>= 1) nn += __shfl_xor_sync(0xffffffffu, nn, o);
    if (lane == 0) w_nn[warp] = nn;
    __syncthreads();
    if (tid == 0) {
        float t = 0.f;
        for (int wv = 0; wv < 8; wv++) t += w_nn[wv];
        g_rnorm[b] = sqrtf(t);
    }
}

// ---------------- K4: top_k emulation + decode + losses ----------------
__global__ __launch_bounds__(256) void k_finalize(const float* __restrict__ y,
                                                  const float* __restrict__ xs,
                                                  const float* __restrict__ ys,
                                                  float* __restrict__ out) {
    const int b = blockIdx.x;
    const int tid = threadIdx.x;

    __shared__ int   s_idx[L0];
    __shared__ float s_w[L0];
    __shared__ int   s_m;
    __shared__ float wred[8];

    if (tid == 0) {
        int   ti[L0]; float tw[L0];
        int m = g_cnt[b];
        for (int j = 0; j < m; j++) { ti[j] = g_idx[b * L0 + j]; tw[j] = g_w[b * L0 + j]; }
        // stable sort: value desc, index asc on ties (matches jax.lax.top_k)
        for (int i = 1; i < m; i++) {
            float wv = tw[i]; int iv = ti[i]; int j = i - 1;
            while (j >= 0 && (tw[j] < wv || (tw[j] == wv && ti[j] > iv))) {
                tw[j + 1] = tw[j]; ti[j + 1] = ti[j]; j--;
            }
            tw[j + 1] = wv; ti[j + 1] = iv;
        }
        // zero-pad with smallest unused indices (top_k tie rule on zeros)
        int k = m, f = 0;
        while (k < L0) {
            bool used = false;
            for (int j = 0; j < m; j++) if (ti[j] == f) { used = true; break; }
            if (!used) { ti[k] = f; tw[k] = 0.f; k++; }
            f++;
        }
        for (int j = 0; j < L0; j++) { s_idx[j] = ti[j]; s_w[j] = tw[j]; }
        s_m = m;
    }
    __syncthreads();

    float* out_w = out;
    float* out_i = out + (size_t)NB * L0;
    float* out_x = out + (size_t)2 * NB * L0;
    float* out_y = out_x + (size_t)NB * ND;
    float* out_l = out_y + (size_t)NB * ND;

    if (tid < L0) {
        out_w[b * L0 + tid] = s_w[tid];
        out_i[b * L0 + tid] = (float)s_idx[tid];
    }

    const int m = s_m;
    float lsum = 0.f;
    for (int d = tid; d < ND; d += 256) {
        float vx = 0.f, vy = 0.f;
        for (int j = 0; j < m; j++) {
            const float w = s_w[j];
            const size_t f = (size_t)s_idx[j];
            vx = fmaf(w, xs[f * ND + d], vx);
            vy = fmaf(w, ys[f * ND + d], vy);
        }
        out_x[(size_t)b * ND + d] = vx;
        out_y[(size_t)b * ND + d] = vy;
        const float e = vy - y[(size_t)b * ND + d];
        lsum = fmaf(e, e, lsum);
    }
#pragma unroll
    for (int o = 16; o; o >>= 1) lsum += __shfl_xor_sync(0xffffffffu, lsum, o);
    if ((tid & 31) == 0) wred[tid >> 5] = lsum;
    __syncthreads();
    if (tid == 0) {
        float t = 0.f;
        for (int i = 0; i < 8; i++) t += wred[i];
        out_l[b] = t;
    }
}

// ---------------- host launcher ----------------
extern "C" void kernel_launch(void* const* d_in, const int* in_sizes, int n_in,
                              void* d_out, int out_size) {
    const float* x = nullptr; const float* y = nullptr;
    const float* xs = nullptr; const float* ys = nullptr;
    for (int i = 0; i < n_in; i++) {
        if (in_sizes[i] == NB * ND) { if (!x) x = (const float*)d_in[i]; else if (!y) y = (const float*)d_in[i]; }
        else if (in_sizes[i] == NF * ND) { if (!xs) xs = (const float*)d_in[i]; else if (!ys) ys = (const float*)d_in[i]; }
    }
    float* out = (float*)d_out;

    cudaFuncSetAttribute(k_gemm_mma, cudaFuncAttributeMaxDynamicSharedMemorySize, GSMEM);

    {   // one-time fp16 cast of xs (idempotent, deterministic)
        size_t n4 = (size_t)NF * ND / 4;
        k_split_xs<<<(unsigned)((n4 + 255) / 256), 256>>>(xs);
    }
    k_init<<<(NB * ND + 255) / 256, 256>>>(x);
    k_norm0<<<NB, 256>>>();

    const int ngrid = (NF / 128) * (NB / 128);   // 256 * 8 = 2048
    for (int t = 0; t < L0; t++) {
        k_gemm_mma<<<ngrid, 256, GSMEM>>>();
        k_step<<<NB, 256>>>(x, xs);
    }
    k_finalize<<<NB, 256>>>(y, xs, ys, out);
}

// round 13
// speedup vs baseline: 1.3935x; 1.3935x over previous
#include <cuda_runtime.h>
#include <cuda_fp16.h>
#include <stdint.h>

// Problem constants (B, D, F, target_l0) — fixed by the dataset.
#define NB 1024
#define ND 1024
#define NF 32768
#define L0 32
#define EPSF 1e-3f
#define NTILE (NF / 128)        // 256 column tiles
#define HB (NB / 2)             // rows per stream half

// ---------------- device state (no allocations allowed) ----------------
__device__ float              g_res[NB * ND];            // residual [B,D] fp32
__device__ float              g_rnorm[NB];               // ||r|| per row
__device__ __half             g_rhi[NB * ND];            // residual fp16
__device__ __half             g_xhi[(size_t)NF * ND];    // xs fp16
__device__ __half             g_C[(size_t)NB * NF];      // approx inner products
__device__ float              g_tmax[NB][NTILE];         // per (row, 128-col tile) max
__device__ float              g_w[NB * L0];
__device__ int                g_idx[NB * L0];
__device__ int                g_cnt[NB];

// ---------------- helpers ----------------
__device__ __forceinline__ uint32_t smem_to_u32(const void* p) {
    uint32_t a;
    asm("{ .reg .u64 t; cvta.to.shared.u64 t, %1; cvt.u32.u64 %0, t; }" : "=r"(a) : "l"(p));
    return a;
}

// pack (value, index): larger key == (larger value, then smaller index)
__device__ __forceinline__ unsigned long long pack_key(float v, int idx) {
    unsigned u = __float_as_uint(v);
    u = (u & 0x80000000u) ? ~u : (u | 0x80000000u);
    return ((unsigned long long)u << 32) | (unsigned)(0xFFFFFFFFu - (unsigned)idx);
}

#define LDSM4(f, addr)                                                                 \
    asm volatile("ldmatrix.sync.aligned.m8n8.x4.shared.b16 {%0,%1,%2,%3}, [%4];"       \
                 : "=r"((f)[0]), "=r"((f)[1]), "=r"((f)[2]), "=r"((f)[3]) : "r"(addr))

#define MMA16816(d, a, b0, b1)                                                         \
    asm volatile("mma.sync.aligned.m16n8k16.row.col.f32.f16.f16.f32 "                  \
                 "{%0,%1,%2,%3},{%4,%5,%6,%7},{%8,%9},{%0,%1,%2,%3};"                  \
                 : "+f"((d)[0]), "+f"((d)[1]), "+f"((d)[2]), "+f"((d)[3])              \
                 : "r"((a)[0]), "r"((a)[1]), "r"((a)[2]), "r"((a)[3]),                 \
                   "r"(b0), "r"(b1))

#define CP_ASYNC16(sa, gp) \
    asm volatile("cp.async.cg.shared.global [%0], [%1], 16;" :: "r"(sa), "l"(gp))
#define CP_COMMIT()  asm volatile("cp.async.commit_group;")
#define CP_WAIT(n)   asm volatile("cp.async.wait_group %0;" :: "n"(n))

// ---------------- K-1: one-time fp16 cast of xs ----------------
__global__ void k_split_xs(const float* __restrict__ xs) {
    size_t i = (size_t)blockIdx.x * blockDim.x + threadIdx.x;
    size_t n4 = (size_t)NF * ND / 4;
    if (i >= n4) return;
    float4 v = ((const float4*)xs)[i];
    __half2* ph = (__half2*)g_xhi;
    ph[i * 2 + 0] = __half2(__float2half_rn(v.x), __float2half_rn(v.y));
    ph[i * 2 + 1] = __half2(__float2half_rn(v.z), __float2half_rn(v.w));
}

// ---------------- K0: init ----------------
__global__ void k_init(const float* __restrict__ x) {
    int i = blockIdx.x * blockDim.x + threadIdx.x;
    if (i < NB * ND) {
        float v = x[i];
        g_res[i] = v;
        g_rhi[i] = __float2half_rn(v);
    }
    if (i < NB) g_cnt[i] = 0;
}

// initial residual norms
__global__ __launch_bounds__(256) void k_norm0() {
    const int b = blockIdx.x;
    const int tid = threadIdx.x;
    __shared__ float wr[8];
    float nn = 0.f;
    for (int d = tid; d < ND; d += 256) {
        float v = g_res[(size_t)b * ND + d];
        nn = fmaf(v, v, nn);
    }
#pragma unroll
    for (int o = 16; o; o >>= 1) nn += __shfl_xor_sync(0xffffffffu, nn, o);
    if ((tid & 31) == 0) wr[tid >> 5] = nn;
    __syncthreads();
    if (tid == 0) {
        float t = 0.f;
        for (int i = 0; i < 8; i++) t += wr[i];
        g_rnorm[b] = sqrtf(t);
    }
}

// ---------------- K2: fp16 hi*hi GEMM (mma.sync), store C fp16 + per-tile max ----------------
// Processes HB=512 rows starting at mbase. CTA tile 128x128, BK=64, 2-stage cp.async.
#define MAT_BYTES 16384                 // 128 rows * 128B
#define STAGE_BYTES (2 * MAT_BYTES)     // aH, bH
#define GSMEM (2 * STAGE_BYTES)         // 65536

__device__ __forceinline__ void fill_stage(uint32_t st, int k0, int tid,
                                           const __half* aH, const __half* bH) {
#pragma unroll
    for (int it = 0; it < 8; it++) {
        const int mat = it >> 2;                 // 0 = A, 1 = B
        const int w = (it & 3) * 256 + tid;      // 0..1023 within matrix
        const int row = w >> 3;
        const int c = w & 7;
        const __half* base = mat ? bH : aH;
        const __half* gp = base + (size_t)row * ND + k0 + c * 8;
        uint32_t off = (uint32_t)(row * 128 + ((c ^ (row & 7)) * 16));
        CP_ASYNC16(st + mat * MAT_BYTES + off, gp);
    }
    CP_COMMIT();
}

__global__ __launch_bounds__(256, 2) void k_gemm_mma(int mbase) {
    extern __shared__ char smem[];
    const uint32_t sb = smem_to_u32(smem);

    const int tid = threadIdx.x;
    const int lane = tid & 31;
    const int wid = tid >> 5;
    const int wm = wid >> 1;      // 0..3 (M)
    const int wn = wid & 1;       // 0..1 (N)
    const int mi = lane >> 3;
    const int r8 = lane & 7;

    const int id = blockIdx.x;
    const int by = id & 3;        // 4 M tiles (half batch); vary fastest -> share B tile in L2
    const int bx = id >> 2;
    const int row0 = mbase + by * 128;
    const int col0 = bx * 128;

    const __half* aH = g_rhi + (size_t)row0 * ND;
    const __half* bH = g_xhi + (size_t)col0 * ND;

    float acc[2][8][4];
#pragma unroll
    for (int i = 0; i < 2; i++)
#pragma unroll
        for (int j = 0; j < 8; j++)
#pragma unroll
            for (int q = 0; q < 4; q++) acc[i][j][q] = 0.f;

    fill_stage(sb, 0, tid, aH, bH);
    fill_stage(sb + STAGE_BYTES, 64, tid, aH, bH);
    CP_WAIT(1);
    __syncthreads();

    int buf = 0;
    for (int cch = 0; cch < 16; cch++) {
        const uint32_t st = sb + buf * STAGE_BYTES;

#pragma unroll
        for (int k16 = 0; k16 < 4; k16++) {
            uint32_t afr[2][4];
#pragma unroll
            for (int mt = 0; mt < 2; mt++) {
                const int row = wm * 32 + mt * 16 + (mi & 1) * 8 + r8;
                const int kc = k16 * 2 + (mi >> 1);
                const uint32_t off = (uint32_t)(row * 128 + ((kc ^ (row & 7)) * 16));
                LDSM4(afr[mt], st + off);
            }
            uint32_t bfr[4][4];
#pragma unroll
            for (int nt = 0; nt < 4; nt++) {
                const int row = wn * 64 + nt * 16 + (mi >> 1) * 8 + r8;
                const int kc = k16 * 2 + (mi & 1);
                const uint32_t off = (uint32_t)(row * 128 + ((kc ^ (row & 7)) * 16));
                LDSM4(bfr[nt], st + MAT_BYTES + off);
            }
#pragma unroll
            for (int mt = 0; mt < 2; mt++)
#pragma unroll
                for (int nt = 0; nt < 4; nt++)
#pragma unroll
                    for (int s = 0; s < 2; s++)
                        MMA16816(acc[mt][nt * 2 + s], afr[mt],
                                 bfr[nt][s * 2], bfr[nt][s * 2 + 1]);
        }

        __syncthreads();
        if (cch + 2 < 16) {
            fill_stage(sb + buf * STAGE_BYTES, (cch + 2) * 64, tid, aH, bH);
            CP_WAIT(1);
        } else {
            CP_WAIT(0);
        }
        __syncthreads();
        buf ^= 1;
    }

    // ---- epilogue 1: store C tile as fp16 ----
    __half2* C2 = (__half2*)g_C;
#pragma unroll
    for (int mt = 0; mt < 2; mt++) {
#pragma unroll
        for (int j = 0; j < 8; j++) {
            const int row = row0 + wm * 32 + mt * 16 + (lane >> 2);
            const int col = col0 + wn * 64 + j * 8 + (lane & 3) * 2;
            C2[(size_t)row * (NF / 2) + (col >> 1)] =
                __half2(__float2half_rn(acc[mt][j][0]), __float2half_rn(acc[mt][j][1]));
            C2[(size_t)(row + 8) * (NF / 2) + (col >> 1)] =
                __half2(__float2half_rn(acc[mt][j][2]), __float2half_rn(acc[mt][j][3]));
        }
    }

    // ---- epilogue 2: per-(row, tile) max of fp32 acc (pre-rounding: tight bound) ----
    float (*s_half)[2] = (float (*)[2])smem;    // stages are dead now
#pragma unroll
    for (int mt = 0; mt < 2; mt++) {
#pragma unroll
        for (int goff = 0; goff < 2; goff++) {
            float mx = -1e30f;
#pragma unroll
            for (int j = 0; j < 8; j++) {
                mx = fmaxf(mx, acc[mt][j][goff * 2 + 0]);
                mx = fmaxf(mx, acc[mt][j][goff * 2 + 1]);
            }
#pragma unroll
            for (int o = 1; o < 4; o <<= 1)
                mx = fmaxf(mx, __shfl_xor_sync(0xffffffffu, mx, o));
            if ((lane & 3) == 0) {
                const int rl = wm * 32 + mt * 16 + goff * 8 + (lane >> 2);
                s_half[rl][wn] = mx;
            }
        }
    }
    __syncthreads();
    if (tid < 128)
        g_tmax[row0 + tid][bx] = fmaxf(s_half[tid][0], s_half[tid][1]);
}

// ---------------- K3: fused rescue + update (one block of 256 per row) ----------------
// Warp-parallel g-pass (8 concurrent row streams), smem c, algebraic rebuild:
// r_new = (r_old - step*c) + sum_{dropped} wtent_j * xs_j.
#define MAXCAND 128
__global__ __launch_bounds__(256) void k_step(const float* __restrict__ x,
                                              const float* __restrict__ xs,
                                              int rbase) {
    const int b = rbase + blockIdx.x;
    const int tid = threadIdx.x;
    const int warp = tid >> 5, lane = tid & 31;

    __shared__ float wr[8];
    __shared__ float s_thr;
    __shared__ int   s_tiles[NTILE];
    __shared__ int   s_nt;
    __shared__ int   s_cand[MAXCAND];
    __shared__ int   s_nc;
    __shared__ unsigned long long s_best;
    __shared__ int   s_idx[L0];
    __shared__ float s_w[L0];
    __shared__ float s_g[L0];
    __shared__ int   s_cnt;
    __shared__ float s_step;
    __shared__ int   s_dropidx[L0];
    __shared__ float s_dropw[L0];
    __shared__ int   s_ndrop;
    __shared__ float s_c[ND];
    __shared__ float w_cc[8], w_cr[8], w_nn[8];

    // ---- A1: global max over 256 tile maxes ----
    const float tv = g_tmax[b][tid];
    float mx = tv;
#pragma unroll
    for (int o = 16; o; o >>= 1) mx = fmaxf(mx, __shfl_xor_sync(0xffffffffu, mx, o));
    if (lane == 0) wr[warp] = mx;
    if (tid == 0) { s_nt = 0; s_nc = 0; s_best = 0ull; s_ndrop = 0; }
    __syncthreads();
    if (tid == 0) {
        float t = -1e30f;
        for (int i = 0; i < 8; i++) t = fmaxf(t, wr[i]);
        const float Bm = 2.0e-3f * g_rnorm[b] + 1e-7f;
        s_thr = t - 2.f * Bm;
    }
    __syncthreads();
    const float thr = s_thr;

    // ---- A2: flag tiles that can contain the exact argmax ----
    if (tv >= thr) { int p = atomicAdd(&s_nt, 1); s_tiles[p] = tid; }
    __syncthreads();
    const int ntl = s_nt;

    // ---- A3: scan flagged tiles for candidates ----
    const __half2* Crow = (const __half2*)g_C + (size_t)b * (NF / 2);
    for (int tt = 0; tt < ntl; tt++) {
        const int tile = s_tiles[tt];
        if (tid < 64) {
            __half2 v = Crow[tile * 64 + tid];
            float a = __half2float(v.x), c = __half2float(v.y);
            if (a >= thr) { int p = atomicAdd(&s_nc, 1); if (p < MAXCAND) s_cand[p] = tile * 128 + 2 * tid; }
            if (c >= thr) { int p = atomicAdd(&s_nc, 1); if (p < MAXCAND) s_cand[p] = tile * 128 + 2 * tid + 1; }
        }
    }
    __syncthreads();
    const int nc = (s_nc < MAXCAND) ? s_nc : MAXCAND;

    // ---- A4: exact fp32 rescore, one warp per candidate ----
    const float* r = g_res + (size_t)b * ND;
    for (int cdx = warp; cdx < nc; cdx += 8) {
        const int f = s_cand[cdx];
        const float* a = xs + (size_t)f * ND;
        float s = 0.f;
        for (int d = lane; d < ND; d += 32) s = fmaf(r[d], a[d], s);
#pragma unroll
        for (int o = 16; o; o >>= 1) s += __shfl_xor_sync(0xffffffffu, s, o);
        if (lane == 0) atomicMax(&s_best, pack_key(s, f));
    }
    __syncthreads();

    // ---- B: build active set ----
    if (tid == 0) {
        int cnt = g_cnt[b];
        for (int j = 0; j < cnt; j++) { s_idx[j] = g_idx[b * L0 + j]; s_w[j] = g_w[b * L0 + j]; }
        int f = (int)(0xFFFFFFFFu - (unsigned)(s_best & 0xFFFFFFFFull));
        bool present = false;
        for (int j = 0; j < cnt; j++) if (s_idx[j] == f) { present = true; break; }
        if (!present) { s_idx[cnt] = f; s_w[cnt] = 0.f; cnt++; }
        s_cnt = cnt;
    }
    __syncthreads();
    const int m = s_cnt;

    // ---- g_j = <r, xs[f_j]>, warp-parallel (8 concurrent streams) ----
    for (int j = warp; j < m; j += 8) {
        const float* a = xs + (size_t)s_idx[j] * ND;
        float s = 0.f;
        for (int d = lane; d < ND; d += 32) s = fmaf(r[d], a[d], s);
#pragma unroll
        for (int o = 16; o; o >>= 1) s += __shfl_xor_sync(0xffffffffu, s, o);
        if (lane == 0) s_g[j] = s;
    }
    __syncthreads();

    // ---- c[d] = sum_j g_j xs_j[d] (kept in smem, xs rows L2-hot); cc, cr ----
    float cc = 0.f, cr = 0.f;
    for (int d = tid; d < ND; d += 256) {
        float c = 0.f;
        for (int j = 0; j < m; j++) c = fmaf(s_g[j], xs[(size_t)s_idx[j] * ND + d], c);
        s_c[d] = c;
        cc = fmaf(c, c, cc);
        cr = fmaf(c, r[d], cr);
    }
#pragma unroll
    for (int o = 16; o; o >>= 1) {
        cc += __shfl_xor_sync(0xffffffffu, cc, o);
        cr += __shfl_xor_sync(0xffffffffu, cr, o);
    }
    if (lane == 0) { w_cc[warp] = cc; w_cr[warp] = cr; }
    __syncthreads();
    if (tid == 0) {
        float tcc = 0.f, tcr = 0.f;
        for (int wv = 0; wv < 8; wv++) { tcc += w_cc[wv]; tcr += w_cr[wv]; }
        s_step = tcr / fmaxf(tcc, EPSF);
    }
    __syncthreads();
    const float step = s_step;

    // ---- relu update + compaction, recording dropped atoms ----
    if (tid == 0) {
        int ncn = 0, nd2 = 0;
        for (int j = 0; j < m; j++) {
            float wt = s_w[j] + step * s_g[j];
            if (wt > 0.f) { s_idx[ncn] = s_idx[j]; s_w[ncn] = wt; ncn++; }
            else          { s_dropidx[nd2] = s_idx[j]; s_dropw[nd2] = wt; nd2++; }
        }
        s_cnt = ncn;
        s_ndrop = nd2;
        g_cnt[b] = ncn;
        for (int j = 0; j < ncn; j++) { g_idx[b * L0 + j] = s_idx[j]; g_w[b * L0 + j] = s_w[j]; }
    }
    __syncthreads();
    const int nd = s_ndrop;

    // ---- algebraic rebuild: r_new = (r_old - step*c) + sum_dropped wtent*xs ----
    float nn = 0.f;
    for (int d = tid; d < ND; d += 256) {
        float v = fmaf(-step, s_c[d], g_res[(size_t)b * ND + d]);
        for (int dq = 0; dq < nd; dq++)
            v = fmaf(s_dropw[dq], xs[(size_t)s_dropidx[dq] * ND + d], v);
        g_res[(size_t)b * ND + d] = v;
        g_rhi[(size_t)b * ND + d] = __float2half_rn(v);
        nn = fmaf(v, v, nn);
    }
#pragma unroll
    for (int o = 16; o; o >>= 1) nn += __shfl_xor_sync(0xffffffffu, nn, o);
    if (lane == 0) w_nn[warp] = nn;
    __syncthreads();
    if (tid == 0) {
        float t = 0.f;
        for (int wv = 0; wv < 8; wv++) t += w_nn[wv];
        g_rnorm[b] = sqrtf(t);
    }
}

// ---------------- K4: top_k emulation + decode + losses ----------------
__global__ __launch_bounds__(256) void k_finalize(const float* __restrict__ y,
                                                  const float* __restrict__ xs,
                                                  const float* __restrict__ ys,
                                                  float* __restrict__ out) {
    const int b = blockIdx.x;
    const int tid = threadIdx.x;

    __shared__ int   s_idx[L0];
    __shared__ float s_w[L0];
    __shared__ int   s_m;
    __shared__ float wred[8];

    if (tid == 0) {
        int   ti[L0]; float tw[L0];
        int m = g_cnt[b];
        for (int j = 0; j < m; j++) { ti[j] = g_idx[b * L0 + j]; tw[j] = g_w[b * L0 + j]; }
        // stable sort: value desc, index asc on ties (matches jax.lax.top_k)
        for (int i = 1; i < m; i++) {
            float wv = tw[i]; int iv = ti[i]; int j = i - 1;
            while (j >= 0 && (tw[j] < wv || (tw[j] == wv && ti[j] > iv))) {
                tw[j + 1] = tw[j]; ti[j + 1] = ti[j]; j--;
            }
            tw[j + 1] = wv; ti[j + 1] = iv;
        }
        // zero-pad with smallest unused indices (top_k tie rule on zeros)
        int k = m, f = 0;
        while (k < L0) {
            bool used = false;
            for (int j = 0; j < m; j++) if (ti[j] == f) { used = true; break; }
            if (!used) { ti[k] = f; tw[k] = 0.f; k++; }
            f++;
        }
        for (int j = 0; j < L0; j++) { s_idx[j] = ti[j]; s_w[j] = tw[j]; }
        s_m = m;
    }
    __syncthreads();

    float* out_w = out;
    float* out_i = out + (size_t)NB * L0;
    float* out_x = out + (size_t)2 * NB * L0;
    float* out_y = out_x + (size_t)NB * ND;
    float* out_l = out_y + (size_t)NB * ND;

    if (tid < L0) {
        out_w[b * L0 + tid] = s_w[tid];
        out_i[b * L0 + tid] = (float)s_idx[tid];
    }

    const int m = s_m;
    float lsum = 0.f;
    for (int d = tid; d < ND; d += 256) {
        float vx = 0.f, vy = 0.f;
        for (int j = 0; j < m; j++) {
            const float w = s_w[j];
            const size_t f = (size_t)s_idx[j];
            vx = fmaf(w, xs[f * ND + d], vx);
            vy = fmaf(w, ys[f * ND + d], vy);
        }
        out_x[(size_t)b * ND + d] = vx;
        out_y[(size_t)b * ND + d] = vy;
        const float e = vy - y[(size_t)b * ND + d];
        lsum = fmaf(e, e, lsum);
    }
#pragma unroll
    for (int o = 16; o; o >>= 1) lsum += __shfl_xor_sync(0xffffffffu, lsum, o);
    if ((tid & 31) == 0) wred[tid >> 5] = lsum;
    __syncthreads();
    if (tid == 0) {
        float t = 0.f;
        for (int i = 0; i < 8; i++) t += wred[i];
        out_l[b] = t;
    }
}

// ---------------- host launcher ----------------
extern "C" void kernel_launch(void* const* d_in, const int* in_sizes, int n_in,
                              void* d_out, int out_size) {
    const float* x = nullptr; const float* y = nullptr;
    const float* xs = nullptr; const float* ys = nullptr;
    for (int i = 0; i < n_in; i++) {
        if (in_sizes[i] == NB * ND) { if (!x) x = (const float*)d_in[i]; else if (!y) y = (const float*)d_in[i]; }
        else if (in_sizes[i] == NF * ND) { if (!xs) xs = (const float*)d_in[i]; else if (!ys) ys = (const float*)d_in[i]; }
    }
    float* out = (float*)d_out;

    cudaFuncSetAttribute(k_gemm_mma, cudaFuncAttributeMaxDynamicSharedMemorySize, GSMEM);

    // Fork/join resources (host-side objects only; no device memory).
    cudaStream_t s1;
    cudaEvent_t eFork, eJoin;
    cudaStreamCreateWithFlags(&s1, cudaStreamNonBlocking);
    cudaEventCreateWithFlags(&eFork, cudaEventDisableTiming);
    cudaEventCreateWithFlags(&eJoin, cudaEventDisableTiming);

    {   // one-time fp16 cast of xs (idempotent, deterministic)
        size_t n4 = (size_t)NF * ND / 4;
        k_split_xs<<<(unsigned)((n4 + 255) / 256), 256>>>(xs);
    }
    k_init<<<(NB * ND + 255) / 256, 256>>>(x);
    k_norm0<<<NB, 256>>>();

    // Fork: half B (rows 512..1023) runs on s1, fully independent of half A.
    cudaEventRecord(eFork, 0);
    cudaStreamWaitEvent(s1, eFork, 0);

    const int hgrid = (NF / 128) * (HB / 128);   // 256 * 4 = 1024 per half
    for (int t = 0; t < L0; t++) {
        k_gemm_mma<<<hgrid, 256, GSMEM, 0>>>(0);
        k_step<<<HB, 256, 0, 0>>>(x, xs, 0);
        k_gemm_mma<<<hgrid, 256, GSMEM, s1>>>(HB);
        k_step<<<HB, 256, 0, s1>>>(x, xs, HB);
    }

    // Join before finalize.
    cudaEventRecord(eJoin, s1);
    cudaStreamWaitEvent(0, eJoin, 0);

    k_finalize<<<NB, 256>>>(y, xs, ys, out);
}

// round 15
// speedup vs baseline: 1.5045x; 1.0796x over previous
#include <cuda_runtime.h>
#include <cuda_fp16.h>
#include <stdint.h>

// Problem constants (B, D, F, target_l0) — fixed by the dataset.
#define NB 1024
#define ND 1024
#define NF 32768
#define L0 32
#define EPSF 1e-3f
#define NTILE (NF / 128)        // 256 column tiles
#define QB (NB / 4)             // rows per stream quarter

// ---------------- device state (no allocations allowed) ----------------
__device__ float              g_res[NB * ND];            // residual [B,D] fp32
__device__ float              g_rnorm[NB];               // ||r|| per row
__device__ __half             g_rhi[NB * ND];            // residual fp16
__device__ __half             g_xhi[(size_t)NF * ND];    // xs fp16
__device__ __half             g_C[(size_t)NB * NF];      // approx inner products
__device__ float              g_tmax[NB][NTILE];         // per (row, 128-col tile) max
__device__ float              g_w[NB * L0];
__device__ int                g_idx[NB * L0];
__device__ int                g_cnt[NB];

// ---------------- helpers ----------------
__device__ __forceinline__ uint32_t smem_to_u32(const void* p) {
    uint32_t a;
    asm("{ .reg .u64 t; cvta.to.shared.u64 t, %1; cvt.u32.u64 %0, t; }" : "=r"(a) : "l"(p));
    return a;
}

// pack (value, index): larger key == (larger value, then smaller index)
__device__ __forceinline__ unsigned long long pack_key(float v, int idx) {
    unsigned u = __float_as_uint(v);
    u = (u & 0x80000000u) ? ~u : (u | 0x80000000u);
    return ((unsigned long long)u << 32) | (unsigned)(0xFFFFFFFFu - (unsigned)idx);
}

#define LDSM4(f, addr)                                                                 \
    asm volatile("ldmatrix.sync.aligned.m8n8.x4.shared.b16 {%0,%1,%2,%3}, [%4];"       \
                 : "=r"((f)[0]), "=r"((f)[1]), "=r"((f)[2]), "=r"((f)[3]) : "r"(addr))

#define MMA16816(d, a, b0, b1)                                                         \
    asm volatile("mma.sync.aligned.m16n8k16.row.col.f32.f16.f16.f32 "                  \
                 "{%0,%1,%2,%3},{%4,%5,%6,%7},{%8,%9},{%0,%1,%2,%3};"                  \
                 : "+f"((d)[0]), "+f"((d)[1]), "+f"((d)[2]), "+f"((d)[3])              \
                 : "r"((a)[0]), "r"((a)[1]), "r"((a)[2]), "r"((a)[3]),                 \
                   "r"(b0), "r"(b1))

#define CP_ASYNC16(sa, gp) \
    asm volatile("cp.async.cg.shared.global [%0], [%1], 16;" :: "r"(sa), "l"(gp))
#define CP_COMMIT()  asm volatile("cp.async.commit_group;")
#define CP_WAIT(n)   asm volatile("cp.async.wait_group %0;" :: "n"(n))

// ---------------- K-1: one-time fp16 cast of xs ----------------
__global__ void k_split_xs(const float* __restrict__ xs) {
    size_t i = (size_t)blockIdx.x * blockDim.x + threadIdx.x;
    size_t n4 = (size_t)NF * ND / 4;
    if (i >= n4) return;
    float4 v = ((const float4*)xs)[i];
    __half2* ph = (__half2*)g_xhi;
    ph[i * 2 + 0] = __half2(__float2half_rn(v.x), __float2half_rn(v.y));
    ph[i * 2 + 1] = __half2(__float2half_rn(v.z), __float2half_rn(v.w));
}

// ---------------- K0: init ----------------
__global__ void k_init(const float* __restrict__ x) {
    int i = blockIdx.x * blockDim.x + threadIdx.x;
    if (i < NB * ND) {
        float v = x[i];
        g_res[i] = v;
        g_rhi[i] = __float2half_rn(v);
    }
    if (i < NB) g_cnt[i] = 0;
}

// initial residual norms
__global__ __launch_bounds__(256) void k_norm0() {
    const int b = blockIdx.x;
    const int tid = threadIdx.x;
    __shared__ float wr[8];
    float nn = 0.f;
    for (int d = tid; d < ND; d += 256) {
        float v = g_res[(size_t)b * ND + d];
        nn = fmaf(v, v, nn);
    }
#pragma unroll
    for (int o = 16; o; o >>= 1) nn += __shfl_xor_sync(0xffffffffu, nn, o);
    if ((tid & 31) == 0) wr[tid >> 5] = nn;
    __syncthreads();
    if (tid == 0) {
        float t = 0.f;
        for (int i = 0; i < 8; i++) t += wr[i];
        g_rnorm[b] = sqrtf(t);
    }
}

// ---------------- K2: fp16 hi*hi GEMM (mma.sync), store C fp16 + per-tile max ----------------
// Processes QB=256 rows starting at mbase. CTA tile 128x128, BK=64, 2-stage cp.async.
#define MAT_BYTES 16384                 // 128 rows * 128B
#define STAGE_BYTES (2 * MAT_BYTES)     // aH, bH
#define GSMEM (2 * STAGE_BYTES)         // 65536

__device__ __forceinline__ void fill_stage(uint32_t st, int k0, int tid,
                                           const __half* aH, const __half* bH) {
#pragma unroll
    for (int it = 0; it < 8; it++) {
        const int mat = it >> 2;                 // 0 = A, 1 = B
        const int w = (it & 3) * 256 + tid;      // 0..1023 within matrix
        const int row = w >> 3;
        const int c = w & 7;
        const __half* base = mat ? bH : aH;
        const __half* gp = base + (size_t)row * ND + k0 + c * 8;
        uint32_t off = (uint32_t)(row * 128 + ((c ^ (row & 7)) * 16));
        CP_ASYNC16(st + mat * MAT_BYTES + off, gp);
    }
    CP_COMMIT();
}

__global__ __launch_bounds__(256, 2) void k_gemm_mma(int mbase) {
    extern __shared__ char smem[];
    const uint32_t sb = smem_to_u32(smem);

    const int tid = threadIdx.x;
    const int lane = tid & 31;
    const int wid = tid >> 5;
    const int wm = wid >> 1;      // 0..3 (M)
    const int wn = wid & 1;       // 0..1 (N)
    const int mi = lane >> 3;
    const int r8 = lane & 7;

    const int id = blockIdx.x;
    const int by = id & 1;        // 2 M tiles (quarter batch); vary fastest -> share B tile in L2
    const int bx = id >> 1;
    const int row0 = mbase + by * 128;
    const int col0 = bx * 128;

    const __half* aH = g_rhi + (size_t)row0 * ND;
    const __half* bH = g_xhi + (size_t)col0 * ND;

    float acc[2][8][4];
#pragma unroll
    for (int i = 0; i < 2; i++)
#pragma unroll
        for (int j = 0; j < 8; j++)
#pragma unroll
            for (int q = 0; q < 4; q++) acc[i][j][q] = 0.f;

    fill_stage(sb, 0, tid, aH, bH);
    fill_stage(sb + STAGE_BYTES, 64, tid, aH, bH);
    CP_WAIT(1);
    __syncthreads();

    int buf = 0;
    for (int cch = 0; cch < 16; cch++) {
        const uint32_t st = sb + buf * STAGE_BYTES;

#pragma unroll
        for (int k16 = 0; k16 < 4; k16++) {
            uint32_t afr[2][4];
#pragma unroll
            for (int mt = 0; mt < 2; mt++) {
                const int row = wm * 32 + mt * 16 + (mi & 1) * 8 + r8;
                const int kc = k16 * 2 + (mi >> 1);
                const uint32_t off = (uint32_t)(row * 128 + ((kc ^ (row & 7)) * 16));
                LDSM4(afr[mt], st + off);
            }
            uint32_t bfr[4][4];
#pragma unroll
            for (int nt = 0; nt < 4; nt++) {
                const int row = wn * 64 + nt * 16 + (mi >> 1) * 8 + r8;
                const int kc = k16 * 2 + (mi & 1);
                const uint32_t off = (uint32_t)(row * 128 + ((kc ^ (row & 7)) * 16));
                LDSM4(bfr[nt], st + MAT_BYTES + off);
            }
#pragma unroll
            for (int mt = 0; mt < 2; mt++)
#pragma unroll
                for (int nt = 0; nt < 4; nt++)
#pragma unroll
                    for (int s = 0; s < 2; s++)
                        MMA16816(acc[mt][nt * 2 + s], afr[mt],
                                 bfr[nt][s * 2], bfr[nt][s * 2 + 1]);
        }

        __syncthreads();
        if (cch + 2 < 16) {
            fill_stage(sb + buf * STAGE_BYTES, (cch + 2) * 64, tid, aH, bH);
            CP_WAIT(1);
        } else {
            CP_WAIT(0);
        }
        __syncthreads();
        buf ^= 1;
    }

    // ---- epilogue 1: store C tile as fp16 ----
    __half2* C2 = (__half2*)g_C;
#pragma unroll
    for (int mt = 0; mt < 2; mt++) {
#pragma unroll
        for (int j = 0; j < 8; j++) {
            const int row = row0 + wm * 32 + mt * 16 + (lane >> 2);
            const int col = col0 + wn * 64 + j * 8 + (lane & 3) * 2;
            C2[(size_t)row * (NF / 2) + (col >> 1)] =
                __half2(__float2half_rn(acc[mt][j][0]), __float2half_rn(acc[mt][j][1]));
            C2[(size_t)(row + 8) * (NF / 2) + (col >> 1)] =
                __half2(__float2half_rn(acc[mt][j][2]), __float2half_rn(acc[mt][j][3]));
        }
    }

    // ---- epilogue 2: per-(row, tile) max of fp32 acc (pre-rounding: tight bound) ----
    float (*s_half)[2] = (float (*)[2])smem;    // stages are dead now
#pragma unroll
    for (int mt = 0; mt < 2; mt++) {
#pragma unroll
        for (int goff = 0; goff < 2; goff++) {
            float mx = -1e30f;
#pragma unroll
            for (int j = 0; j < 8; j++) {
                mx = fmaxf(mx, acc[mt][j][goff * 2 + 0]);
                mx = fmaxf(mx, acc[mt][j][goff * 2 + 1]);
            }
#pragma unroll
            for (int o = 1; o < 4; o <<= 1)
                mx = fmaxf(mx, __shfl_xor_sync(0xffffffffu, mx, o));
            if ((lane & 3) == 0) {
                const int rl = wm * 32 + mt * 16 + goff * 8 + (lane >> 2);
                s_half[rl][wn] = mx;
            }
        }
    }
    __syncthreads();
    if (tid < 128)
        g_tmax[row0 + tid][bx] = fmaxf(s_half[tid][0], s_half[tid][1]);
}

// ---------------- K3: fused rescue + update (one block of 256 per row) ----------------
// Warp-parallel g-pass (8 concurrent row streams), smem c, algebraic rebuild:
// r_new = (r_old - step*c) + sum_{dropped} wtent_j * xs_j.
#define MAXCAND 128
__global__ __launch_bounds__(256) void k_step(const float* __restrict__ x,
                                              const float* __restrict__ xs,
                                              int rbase) {
    const int b = rbase + blockIdx.x;
    const int tid = threadIdx.x;
    const int warp = tid >> 5, lane = tid & 31;

    __shared__ float wr[8];
    __shared__ float s_thr;
    __shared__ int   s_tiles[NTILE];
    __shared__ int   s_nt;
    __shared__ int   s_cand[MAXCAND];
    __shared__ int   s_nc;
    __shared__ unsigned long long s_best;
    __shared__ int   s_idx[L0];
    __shared__ float s_w[L0];
    __shared__ float s_g[L0];
    __shared__ int   s_cnt;
    __shared__ float s_step;
    __shared__ int   s_dropidx[L0];
    __shared__ float s_dropw[L0];
    __shared__ int   s_ndrop;
    __shared__ float s_c[ND];
    __shared__ float w_cc[8], w_cr[8], w_nn[8];

    // ---- A1: global max over 256 tile maxes ----
    const float tv = g_tmax[b][tid];
    float mx = tv;
#pragma unroll
    for (int o = 16; o; o >>= 1) mx = fmaxf(mx, __shfl_xor_sync(0xffffffffu, mx, o));
    if (lane == 0) wr[warp] = mx;
    if (tid == 0) { s_nt = 0; s_nc = 0; s_best = 0ull; s_ndrop = 0; }
    __syncthreads();
    if (tid == 0) {
        float t = -1e30f;
        for (int i = 0; i < 8; i++) t = fmaxf(t, wr[i]);
        const float Bm = 2.0e-3f * g_rnorm[b] + 1e-7f;
        s_thr = t - 2.f * Bm;
    }
    __syncthreads();
    const float thr = s_thr;

    // ---- A2: flag tiles that can contain the exact argmax ----
    if (tv >= thr) { int p = atomicAdd(&s_nt, 1); s_tiles[p] = tid; }
    __syncthreads();
    const int ntl = s_nt;

    // ---- A3: scan flagged tiles for candidates ----
    const __half2* Crow = (const __half2*)g_C + (size_t)b * (NF / 2);
    for (int tt = 0; tt < ntl; tt++) {
        const int tile = s_tiles[tt];
        if (tid < 64) {
            __half2 v = Crow[tile * 64 + tid];
            float a = __half2float(v.x), c = __half2float(v.y);
            if (a >= thr) { int p = atomicAdd(&s_nc, 1); if (p < MAXCAND) s_cand[p] = tile * 128 + 2 * tid; }
            if (c >= thr) { int p = atomicAdd(&s_nc, 1); if (p < MAXCAND) s_cand[p] = tile * 128 + 2 * tid + 1; }
        }
    }
    __syncthreads();
    const int nc = (s_nc < MAXCAND) ? s_nc : MAXCAND;

    // ---- A4: exact fp32 rescore, one warp per candidate ----
    const float* r = g_res + (size_t)b * ND;
    for (int cdx = warp; cdx < nc; cdx += 8) {
        const int f = s_cand[cdx];
        const float* a = xs + (size_t)f * ND;
        float s = 0.f;
        for (int d = lane; d < ND; d += 32) s = fmaf(r[d], a[d], s);
#pragma unroll
        for (int o = 16; o; o >>= 1) s += __shfl_xor_sync(0xffffffffu, s, o);
        if (lane == 0) atomicMax(&s_best, pack_key(s, f));
    }
    __syncthreads();

    // ---- B: build active set ----
    if (tid == 0) {
        int cnt = g_cnt[b];
        for (int j = 0; j < cnt; j++) { s_idx[j] = g_idx[b * L0 + j]; s_w[j] = g_w[b * L0 + j]; }
        int f = (int)(0xFFFFFFFFu - (unsigned)(s_best & 0xFFFFFFFFull));
        bool present = false;
        for (int j = 0; j < cnt; j++) if (s_idx[j] == f) { present = true; break; }
        if (!present) { s_idx[cnt] = f; s_w[cnt] = 0.f; cnt++; }
        s_cnt = cnt;
    }
    __syncthreads();
    const int m = s_cnt;

    // ---- g_j = <r, xs[f_j]>, warp-parallel (8 concurrent streams) ----
    for (int j = warp; j < m; j += 8) {
        const float* a = xs + (size_t)s_idx[j] * ND;
        float s = 0.f;
        for (int d = lane; d < ND; d += 32) s = fmaf(r[d], a[d], s);
#pragma unroll
        for (int o = 16; o; o >>= 1) s += __shfl_xor_sync(0xffffffffu, s, o);
        if (lane == 0) s_g[j] = s;
    }
    __syncthreads();

    // ---- c[d] = sum_j g_j xs_j[d] (kept in smem, xs rows L2-hot); cc, cr ----
    float cc = 0.f, cr = 0.f;
    for (int d = tid; d < ND; d += 256) {
        float c = 0.f;
        for (int j = 0; j < m; j++) c = fmaf(s_g[j], xs[(size_t)s_idx[j] * ND + d], c);
        s_c[d] = c;
        cc = fmaf(c, c, cc);
        cr = fmaf(c, r[d], cr);
    }
#pragma unroll
    for (int o = 16; o; o >>= 1) {
        cc += __shfl_xor_sync(0xffffffffu, cc, o);
        cr += __shfl_xor_sync(0xffffffffu, cr, o);
    }
    if (lane == 0) { w_cc[warp] = cc; w_cr[warp] = cr; }
    __syncthreads();
    if (tid == 0) {
        float tcc = 0.f, tcr = 0.f;
        for (int wv = 0; wv < 8; wv++) { tcc += w_cc[wv]; tcr += w_cr[wv]; }
        s_step = tcr / fmaxf(tcc, EPSF);
    }
    __syncthreads();
    const float step = s_step;

    // ---- relu update + compaction, recording dropped atoms ----
    if (tid == 0) {
        int ncn = 0, nd2 = 0;
        for (int j = 0; j < m; j++) {
            float wt = s_w[j] + step * s_g[j];
            if (wt > 0.f) { s_idx[ncn] = s_idx[j]; s_w[ncn] = wt; ncn++; }
            else          { s_dropidx[nd2] = s_idx[j]; s_dropw[nd2] = wt; nd2++; }
        }
        s_cnt = ncn;
        s_ndrop = nd2;
        g_cnt[b] = ncn;
        for (int j = 0; j < ncn; j++) { g_idx[b * L0 + j] = s_idx[j]; g_w[b * L0 + j] = s_w[j]; }
    }
    __syncthreads();
    const int nd = s_ndrop;

    // ---- algebraic rebuild: r_new = (r_old - step*c) + sum_dropped wtent*xs ----
    float nn = 0.f;
    for (int d = tid; d < ND; d += 256) {
        float v = fmaf(-step, s_c[d], g_res[(size_t)b * ND + d]);
        for (int dq = 0; dq < nd; dq++)
            v = fmaf(s_dropw[dq], xs[(size_t)s_dropidx[dq] * ND + d], v);
        g_res[(size_t)b * ND + d] = v;
        g_rhi[(size_t)b * ND + d] = __float2half_rn(v);
        nn = fmaf(v, v, nn);
    }
#pragma unroll
    for (int o = 16; o; o >>= 1) nn += __shfl_xor_sync(0xffffffffu, nn, o);
    if (lane == 0) w_nn[warp] = nn;
    __syncthreads();
    if (tid == 0) {
        float t = 0.f;
        for (int wv = 0; wv < 8; wv++) t += w_nn[wv];
        g_rnorm[b] = sqrtf(t);
    }
}

// ---------------- K4: top_k emulation + decode + losses ----------------
__global__ __launch_bounds__(256) void k_finalize(const float* __restrict__ y,
                                                  const float* __restrict__ xs,
                                                  const float* __restrict__ ys,
                                                  float* __restrict__ out) {
    const int b = blockIdx.x;
    const int tid = threadIdx.x;

    __shared__ int   s_idx[L0];
    __shared__ float s_w[L0];
    __shared__ int   s_m;
    __shared__ float wred[8];

    if (tid == 0) {
        int   ti[L0]; float tw[L0];
        int m = g_cnt[b];
        for (int j = 0; j < m; j++) { ti[j] = g_idx[b * L0 + j]; tw[j] = g_w[b * L0 + j]; }
        // stable sort: value desc, index asc on ties (matches jax.lax.top_k)
        for (int i = 1; i < m; i++) {
            float wv = tw[i]; int iv = ti[i]; int j = i - 1;
            while (j >= 0 && (tw[j] < wv || (tw[j] == wv && ti[j] > iv))) {
                tw[j + 1] = tw[j]; ti[j + 1] = ti[j]; j--;
            }
            tw[j + 1] = wv; ti[j + 1] = iv;
        }
        // zero-pad with smallest unused indices (top_k tie rule on zeros)
        int k = m, f = 0;
        while (k < L0) {
            bool used = false;
            for (int j = 0; j < m; j++) if (ti[j] == f) { used = true; break; }
            if (!used) { ti[k] = f; tw[k] = 0.f; k++; }
            f++;
        }
        for (int j = 0; j < L0; j++) { s_idx[j] = ti[j]; s_w[j] = tw[j]; }
        s_m = m;
    }
    __syncthreads();

    float* out_w = out;
    float* out_i = out + (size_t)NB * L0;
    float* out_x = out + (size_t)2 * NB * L0;
    float* out_y = out_x + (size_t)NB * ND;
    float* out_l = out_y + (size_t)NB * ND;

    if (tid < L0) {
        out_w[b * L0 + tid] = s_w[tid];
        out_i[b * L0 + tid] = (float)s_idx[tid];
    }

    const int m = s_m;
    float lsum = 0.f;
    for (int d = tid; d < ND; d += 256) {
        float vx = 0.f, vy = 0.f;
        for (int j = 0; j < m; j++) {
            const float w = s_w[j];
            const size_t f = (size_t)s_idx[j];
            vx = fmaf(w, xs[f * ND + d], vx);
            vy = fmaf(w, ys[f * ND + d], vy);
        }
        out_x[(size_t)b * ND + d] = vx;
        out_y[(size_t)b * ND + d] = vy;
        const float e = vy - y[(size_t)b * ND + d];
        lsum = fmaf(e, e, lsum);
    }
#pragma unroll
    for (int o = 16; o; o >>= 1) lsum += __shfl_xor_sync(0xffffffffu, lsum, o);
    if ((tid & 31) == 0) wred[tid >> 5] = lsum;
    __syncthreads();
    if (tid == 0) {
        float t = 0.f;
        for (int i = 0; i < 8; i++) t += wred[i];
        out_l[b] = t;
    }
}

// ---------------- host launcher ----------------
extern "C" void kernel_launch(void* const* d_in, const int* in_sizes, int n_in,
                              void* d_out, int out_size) {
    const float* x = nullptr; const float* y = nullptr;
    const float* xs = nullptr; const float* ys = nullptr;
    for (int i = 0; i < n_in; i++) {
        if (in_sizes[i] == NB * ND) { if (!x) x = (const float*)d_in[i]; else if (!y) y = (const float*)d_in[i]; }
        else if (in_sizes[i] == NF * ND) { if (!xs) xs = (const float*)d_in[i]; else if (!ys) ys = (const float*)d_in[i]; }
    }
    float* out = (float*)d_out;

    // Streams/events cached across calls: created ONCE (during the correctness
    // run, outside graph capture) so the capture call performs no allocation.
    // Work launched per call is identical and deterministic.
    static cudaStream_t s[4] = {0, 0, 0, 0};
    static cudaEvent_t eFork = nullptr, eJoin[4] = {nullptr, nullptr, nullptr, nullptr};
    if (eFork == nullptr) {
        cudaFuncSetAttribute(k_gemm_mma, cudaFuncAttributeMaxDynamicSharedMemorySize, GSMEM);
        for (int q = 1; q < 4; q++) cudaStreamCreateWithFlags(&s[q], cudaStreamNonBlocking);
        cudaEventCreateWithFlags(&eFork, cudaEventDisableTiming);
        for (int q = 1; q < 4; q++) cudaEventCreateWithFlags(&eJoin[q], cudaEventDisableTiming);
    }

    {   // one-time fp16 cast of xs (idempotent, deterministic)
        size_t n4 = (size_t)NF * ND / 4;
        k_split_xs<<<(unsigned)((n4 + 255) / 256), 256>>>(xs);
    }
    k_init<<<(NB * ND + 255) / 256, 256>>>(x);
    k_norm0<<<NB, 256>>>();

    // Fork: quarters 1..3 wait on shared prologue.
    cudaEventRecord(eFork, 0);
    for (int q = 1; q < 4; q++) cudaStreamWaitEvent(s[q], eFork, 0);

    const int qgrid = (NF / 128) * (QB / 128);   // 256 * 2 = 512 per quarter
    for (int t = 0; t < L0; t++) {
        for (int q = 0; q < 4; q++) {
            k_gemm_mma<<<qgrid, 256, GSMEM, s[q]>>>(q * QB);
            k_step<<<QB, 256, 0, s[q]>>>(x, xs, q * QB);
        }
    }

    // Join before finalize.
    for (int q = 1; q < 4; q++) {
        cudaEventRecord(eJoin[q], s[q]);
        cudaStreamWaitEvent(0, eJoin[q], 0);
    }

    k_finalize<<<NB, 256>>>(y, xs, ys, out);
}